// round 10
// baseline (speedup 1.0000x reference)
#include <cuda_runtime.h>

#define N_USERS 100000
#define N_ITEMS 50000
#define N_ROWS  150000          // users then items, matching d_out layout
#define NNZ_C   1600000
#define DIM     64

#define NB_U    1563            // ceil(100000/64) user-gemm blocks
#define NB_I    782             // ceil(50000/64)  item-gemm blocks
#define NB_Z    147             // zeroing blocks: 147*256 int4 >= 37500 int4

#define CAP_U   96              // max user degree (Poisson(16): P(>=96) ~ 1e-40)
#define CAP_I   128             // max item degree (Poisson(32))

// ---- device scratch (no-alloc rule) ----
__device__ float g_xw_user[(size_t)N_USERS * DIM];        // 25.6 MB
__device__ float g_xw_item[(size_t)N_ITEMS * DIM];        // 12.8 MB
__device__ int   g_cnt[N_ROWS];                           // degree cursors
__device__ int2  g_perm_u[(size_t)N_USERS * CAP_U];       // 76.8 MB (src_item, val)
__device__ int2  g_perm_i[(size_t)N_ITEMS * CAP_I];       // 51.2 MB (src_user, val)

// ---------------------------------------------------------------------------
// Both dense GEMMs + g_cnt zeroing in one launch:
//   blocks [0, NB_U)            -> user GEMM tiles
//   blocks [NB_U, NB_U+NB_I)    -> item GEMM tiles
//   blocks [NB_U+NB_I, +NB_Z)   -> zero g_cnt (int4 stores)
// Y = X @ W (K=N=64), fp32. 64x64 tile, 4x4 register tile per thread.
// ---------------------------------------------------------------------------
__global__ __launch_bounds__(256) void gemm_zero_kernel(
    const float* __restrict__ user_x, const float* __restrict__ user_w,
    const float* __restrict__ item_x, const float* __restrict__ item_w)
{
    const int tid = threadIdx.x;
    const int b   = blockIdx.x;

    if (b >= NB_U + NB_I) {
        // ---- zero g_cnt ----
        int i = (b - (NB_U + NB_I)) * 256 + tid;       // int4 index
        if (i < N_ROWS / 4) ((int4*)g_cnt)[i] = make_int4(0, 0, 0, 0);
        return;
    }

    __shared__ float Ws[64 * 64];
    __shared__ float Xt[64 * 68];

    const bool is_item = (b >= NB_U);
    const int  gb      = is_item ? (b - NB_U) : b;
    const int  nrows   = is_item ? N_ITEMS : N_USERS;
    const float* X     = is_item ? item_x : user_x;
    const float* W     = is_item ? item_w : user_w;
    float*       Y     = is_item ? g_xw_item : g_xw_user;
    const int  row0    = gb * 64;

    {
        const float4* W4  = (const float4*)W;
        float4*       Ws4 = (float4*)Ws;
        #pragma unroll
        for (int i = 0; i < 4; i++) Ws4[tid + i * 256] = W4[tid + i * 256];
    }
    #pragma unroll
    for (int i = 0; i < 4; i++) {
        int idx = tid + i * 256;
        int r   = idx >> 4;
        int k4  = (idx & 15) * 4;
        float4 v = make_float4(0.f, 0.f, 0.f, 0.f);
        if (row0 + r < nrows)
            v = *(const float4*)(X + (size_t)(row0 + r) * DIM + k4);
        Xt[(k4 + 0) * 68 + r] = v.x;
        Xt[(k4 + 1) * 68 + r] = v.y;
        Xt[(k4 + 2) * 68 + r] = v.z;
        Xt[(k4 + 3) * 68 + r] = v.w;
    }
    __syncthreads();

    const int tx = tid & 15;
    const int ty = tid >> 4;

    float acc[4][4] = {};
    #pragma unroll 16
    for (int k = 0; k < 64; k++) {
        float4 a  = *(const float4*)&Xt[k * 68 + ty * 4];
        float4 bq = *(const float4*)&Ws[k * 64 + tx * 4];
        float av[4] = {a.x, a.y, a.z, a.w};
        float bv[4] = {bq.x, bq.y, bq.z, bq.w};
        #pragma unroll
        for (int i = 0; i < 4; i++)
            #pragma unroll
            for (int j = 0; j < 4; j++)
                acc[i][j] += av[i] * bv[j];
    }

    #pragma unroll
    for (int i = 0; i < 4; i++) {
        int r = row0 + ty * 4 + i;
        if (r < nrows)
            *(float4*)(Y + (size_t)r * DIM + tx * 4) =
                make_float4(acc[i][0], acc[i][1], acc[i][2], acc[i][3]);
    }
}

// ---------------------------------------------------------------------------
// Bucket edges, BOTH directions in one pass. 1 edge/thread (latency play:
// maximize independent atomic+store chains in flight).
// ---------------------------------------------------------------------------
__global__ __launch_bounds__(256) void perm_both_kernel(
    const int* __restrict__ rows, const int* __restrict__ cols,
    const float* __restrict__ vals)
{
    int e = blockIdx.x * blockDim.x + threadIdx.x;
    if (e >= NNZ_C) return;
    int r = rows[e];
    int c = cols[e];
    int v = __float_as_int(vals[e]);
    int s0 = atomicAdd(&g_cnt[r], 1);
    g_perm_u[(size_t)r * CAP_U + s0] = make_int2(c, v);
    int s1 = atomicAdd(&g_cnt[N_USERS + c], 1);
    g_perm_i[(size_t)c * CAP_I + s1] = make_int2(r, v);
}

// ---------------------------------------------------------------------------
// SpMM gather: one warp per output row, fp32 sources, no converts.
// 8-lane groups (g = lane>>3) each process TWO edges per iteration (k, k+4)
// into independent accumulator sets (ILP/MLP). All 8 lanes of a group load
// the same perm entry (L1 broadcast); each lane owns 8 columns via 2 LDG.128.
// Cross-group shfl_xor reduction, fused ReLU.
// ---------------------------------------------------------------------------
__global__ __launch_bounds__(256) void spmm_gather_kernel(float* __restrict__ out)
{
    const int wid  = (blockIdx.x * blockDim.x + threadIdx.x) >> 5;
    const int lane = threadIdx.x & 31;
    if (wid >= N_ROWS) return;

    const int g  = lane >> 3;
    const int l8 = lane & 7;

    const int n = g_cnt[wid];
    const int2* __restrict__ bkt;
    const float* __restrict__ src;
    if (wid < N_USERS) {
        bkt = g_perm_u + (size_t)wid * CAP_U;
        src = g_xw_item;
    } else {
        bkt = g_perm_i + (size_t)(wid - N_USERS) * CAP_I;
        src = g_xw_user;
    }

    float a0 = 0.f, a1 = 0.f, a2 = 0.f, a3 = 0.f;
    float a4 = 0.f, a5 = 0.f, a6 = 0.f, a7 = 0.f;
    float b0 = 0.f, b1 = 0.f, b2 = 0.f, b3 = 0.f;
    float b4 = 0.f, b5 = 0.f, b6 = 0.f, b7 = 0.f;

    for (int k = g; k < n; k += 8) {
        // edge A (always valid: k < n)
        int2 pA = __ldg(bkt + k);
        // edge B (predicated; idx 0 is a safe dummy row, vB = 0)
        const bool hasB = (k + 4) < n;
        int2 pB = hasB ? __ldg(bkt + k + 4) : make_int2(0, 0);

        const float vA = __int_as_float(pA.y);
        const float vB = __int_as_float(pB.y);
        const float4* sA = (const float4*)(src + (size_t)pA.x * DIM) + l8 * 2;
        const float4* sB = (const float4*)(src + (size_t)pB.x * DIM) + l8 * 2;
        float4 A0 = __ldg(sA);
        float4 A1 = __ldg(sA + 1);
        float4 B0 = __ldg(sB);
        float4 B1 = __ldg(sB + 1);

        a0 += vA * A0.x; a1 += vA * A0.y; a2 += vA * A0.z; a3 += vA * A0.w;
        a4 += vA * A1.x; a5 += vA * A1.y; a6 += vA * A1.z; a7 += vA * A1.w;
        b0 += vB * B0.x; b1 += vB * B0.y; b2 += vB * B0.z; b3 += vB * B0.w;
        b4 += vB * B1.x; b5 += vB * B1.y; b6 += vB * B1.z; b7 += vB * B1.w;
    }

    a0 += b0; a1 += b1; a2 += b2; a3 += b3;
    a4 += b4; a5 += b5; a6 += b6; a7 += b7;

    // sum across the 4 edge-groups (lanes l8, l8+8, l8+16, l8+24 share cols)
    a0 += __shfl_xor_sync(0xffffffffu, a0, 8);  a0 += __shfl_xor_sync(0xffffffffu, a0, 16);
    a1 += __shfl_xor_sync(0xffffffffu, a1, 8);  a1 += __shfl_xor_sync(0xffffffffu, a1, 16);
    a2 += __shfl_xor_sync(0xffffffffu, a2, 8);  a2 += __shfl_xor_sync(0xffffffffu, a2, 16);
    a3 += __shfl_xor_sync(0xffffffffu, a3, 8);  a3 += __shfl_xor_sync(0xffffffffu, a3, 16);
    a4 += __shfl_xor_sync(0xffffffffu, a4, 8);  a4 += __shfl_xor_sync(0xffffffffu, a4, 16);
    a5 += __shfl_xor_sync(0xffffffffu, a5, 8);  a5 += __shfl_xor_sync(0xffffffffu, a5, 16);
    a6 += __shfl_xor_sync(0xffffffffu, a6, 8);  a6 += __shfl_xor_sync(0xffffffffu, a6, 16);
    a7 += __shfl_xor_sync(0xffffffffu, a7, 8);  a7 += __shfl_xor_sync(0xffffffffu, a7, 16);

    if (g == 0) {
        float4* op = (float4*)(out + (size_t)wid * DIM) + l8 * 2;
        op[0] = make_float4(fmaxf(a0, 0.f), fmaxf(a1, 0.f),
                            fmaxf(a2, 0.f), fmaxf(a3, 0.f));
        op[1] = make_float4(fmaxf(a4, 0.f), fmaxf(a5, 0.f),
                            fmaxf(a6, 0.f), fmaxf(a7, 0.f));
    }
}

// ---------------------------------------------------------------------------
extern "C" void kernel_launch(void* const* d_in, const int* in_sizes, int n_in,
                              void* d_out, int out_size)
{
    const float* user_x  = (const float*)d_in[0];
    const float* item_x  = (const float*)d_in[1];
    const float* user_w  = (const float*)d_in[2];
    const float* item_w  = (const float*)d_in[3];
    const int*   ui_rows = (const int*)d_in[4];
    const int*   ui_cols = (const int*)d_in[5];
    const float* ui_vals = (const float*)d_in[6];

    float* out = (float*)d_out;

    // k1: both dense GEMMs + zero g_cnt
    gemm_zero_kernel<<<NB_U + NB_I + NB_Z, 256>>>(user_x, user_w, item_x, item_w);

    // k2: bucket edges, both directions, one pass
    perm_both_kernel<<<(NNZ_C + 255) / 256, 256>>>(ui_rows, ui_cols, ui_vals);

    // k3: gather SpMM with fused ReLU (writes every output row)
    spmm_gather_kernel<<<(N_ROWS * 32 + 255) / 256, 256>>>(out);
}

// round 11
// speedup vs baseline: 1.1880x; 1.1880x over previous
#include <cuda_runtime.h>
#include <cuda_fp16.h>

#define N_USERS 100000
#define N_ITEMS 50000
#define N_ROWS  150000          // users then items, matching d_out layout
#define NNZ_C   1600000
#define DIM     64

#define NB_U    1563            // ceil(100000/64) user-gemm blocks
#define NB_I    782             // ceil(50000/64)  item-gemm blocks

#define CAP_U   96              // max user degree (Poisson(16): P(>=96) ~ 1e-40)
#define CAP_I   128             // max item degree (Poisson(32))

// ---- device scratch (no-alloc rule) ----
__device__ __half g_xw_user[(size_t)N_USERS * DIM];        // 12.8 MB
__device__ __half g_xw_item[(size_t)N_ITEMS * DIM];        //  6.4 MB
__device__ int    g_cnt[N_ROWS];                           // degree cursors
__device__ int2   g_perm_u[(size_t)N_USERS * CAP_U];       // 76.8 MB (src_item, val)
__device__ int2   g_perm_i[(size_t)N_ITEMS * CAP_I];       // 51.2 MB (src_user, val)

// ---------------------------------------------------------------------------
// Both dense GEMMs in one launch: blocks [0,NB_U) -> user, rest -> item.
// Y = X @ W (K=N=64), fp32 compute, fp16 output. 64x64 tile, 4x4 per thread.
// ---------------------------------------------------------------------------
__global__ __launch_bounds__(256) void gemm_both_kernel(
    const float* __restrict__ user_x, const float* __restrict__ user_w,
    const float* __restrict__ item_x, const float* __restrict__ item_w)
{
    __shared__ float Ws[64 * 64];
    __shared__ float Xt[64 * 68];

    const int  tid     = threadIdx.x;
    const int  b       = blockIdx.x;
    const bool is_item = (b >= NB_U);
    const int  gb      = is_item ? (b - NB_U) : b;
    const int  nrows   = is_item ? N_ITEMS : N_USERS;
    const float* X     = is_item ? item_x : user_x;
    const float* W     = is_item ? item_w : user_w;
    __half*      Y     = is_item ? g_xw_item : g_xw_user;
    const int  row0    = gb * 64;

    {
        const float4* W4  = (const float4*)W;
        float4*       Ws4 = (float4*)Ws;
        #pragma unroll
        for (int i = 0; i < 4; i++) Ws4[tid + i * 256] = W4[tid + i * 256];
    }
    #pragma unroll
    for (int i = 0; i < 4; i++) {
        int idx = tid + i * 256;
        int r   = idx >> 4;
        int k4  = (idx & 15) * 4;
        float4 v = make_float4(0.f, 0.f, 0.f, 0.f);
        if (row0 + r < nrows)
            v = *(const float4*)(X + (size_t)(row0 + r) * DIM + k4);
        Xt[(k4 + 0) * 68 + r] = v.x;
        Xt[(k4 + 1) * 68 + r] = v.y;
        Xt[(k4 + 2) * 68 + r] = v.z;
        Xt[(k4 + 3) * 68 + r] = v.w;
    }
    __syncthreads();

    const int tx = tid & 15;
    const int ty = tid >> 4;

    float acc[4][4] = {};
    #pragma unroll 16
    for (int k = 0; k < 64; k++) {
        float4 a  = *(const float4*)&Xt[k * 68 + ty * 4];
        float4 bq = *(const float4*)&Ws[k * 64 + tx * 4];
        float av[4] = {a.x, a.y, a.z, a.w};
        float bv[4] = {bq.x, bq.y, bq.z, bq.w};
        #pragma unroll
        for (int i = 0; i < 4; i++)
            #pragma unroll
            for (int j = 0; j < 4; j++)
                acc[i][j] += av[i] * bv[j];
    }

    #pragma unroll
    for (int i = 0; i < 4; i++) {
        int r = row0 + ty * 4 + i;
        if (r < nrows) {
            __half2* Yp = (__half2*)(Y + (size_t)r * DIM + tx * 4);
            Yp[0] = __floats2half2_rn(acc[i][0], acc[i][1]);
            Yp[1] = __floats2half2_rn(acc[i][2], acc[i][3]);
        }
    }
}

// ---------------------------------------------------------------------------
// Bucket edges, user direction: slot via atomic bump of g_cnt[r].
// 1 edge / thread -> max latency hiding for the atomic+scattered-store pair.
// ---------------------------------------------------------------------------
__global__ __launch_bounds__(256) void perm_user_kernel(
    const int* __restrict__ rows, const int* __restrict__ cols,
    const float* __restrict__ vals)
{
    int e = blockIdx.x * blockDim.x + threadIdx.x;
    if (e >= NNZ_C) return;
    int r = rows[e];
    int slot = atomicAdd(&g_cnt[r], 1);
    g_perm_u[(size_t)r * CAP_U + slot] = make_int2(cols[e], __float_as_int(vals[e]));
}

// Bucket edges, item direction.
__global__ __launch_bounds__(256) void perm_item_kernel(
    const int* __restrict__ rows, const int* __restrict__ cols,
    const float* __restrict__ vals)
{
    int e = blockIdx.x * blockDim.x + threadIdx.x;
    if (e >= NNZ_C) return;
    int c = cols[e];
    int slot = atomicAdd(&g_cnt[N_USERS + c], 1);
    g_perm_i[(size_t)c * CAP_I + slot] = make_int2(rows[e], __float_as_int(vals[e]));
}

// ---------------------------------------------------------------------------
// SpMM gather: one warp per output row. 8-lane groups (g = lane>>3) each
// process one edge per iteration; all 8 lanes of a group load the same perm
// entry (L1 broadcast) -- no shuffles in the hot loop. Each lane owns 8
// columns: one LDG.128 covers 8 fp16 values. fp32 accumulation, cross-group
// shfl_xor reduction, fused ReLU.
// ---------------------------------------------------------------------------
__global__ __launch_bounds__(256) void spmm_gather_kernel(float* __restrict__ out)
{
    const int wid  = (blockIdx.x * blockDim.x + threadIdx.x) >> 5;
    const int lane = threadIdx.x & 31;
    if (wid >= N_ROWS) return;

    const int g  = lane >> 3;
    const int l8 = lane & 7;

    const int n = g_cnt[wid];
    const int2* __restrict__ bkt;
    const __half* __restrict__ src;
    if (wid < N_USERS) {
        bkt = g_perm_u + (size_t)wid * CAP_U;
        src = g_xw_item;
    } else {
        bkt = g_perm_i + (size_t)(wid - N_USERS) * CAP_I;
        src = g_xw_user;
    }

    float a0 = 0.f, a1 = 0.f, a2 = 0.f, a3 = 0.f;
    float a4 = 0.f, a5 = 0.f, a6 = 0.f, a7 = 0.f;

    for (int k = g; k < n; k += 4) {
        int2 p = __ldg(bkt + k);                       // broadcast within group
        const float v = __int_as_float(p.y);
        uint4 h = __ldg((const uint4*)(src + (size_t)p.x * DIM) + l8);
        float2 f0 = __half22float2(*(__half2*)&h.x);
        float2 f1 = __half22float2(*(__half2*)&h.y);
        float2 f2 = __half22float2(*(__half2*)&h.z);
        float2 f3 = __half22float2(*(__half2*)&h.w);
        a0 += v * f0.x; a1 += v * f0.y;
        a2 += v * f1.x; a3 += v * f1.y;
        a4 += v * f2.x; a5 += v * f2.y;
        a6 += v * f3.x; a7 += v * f3.y;
    }

    // sum across the 4 edge-groups (lanes l8, l8+8, l8+16, l8+24 share cols)
    a0 += __shfl_xor_sync(0xffffffffu, a0, 8);  a0 += __shfl_xor_sync(0xffffffffu, a0, 16);
    a1 += __shfl_xor_sync(0xffffffffu, a1, 8);  a1 += __shfl_xor_sync(0xffffffffu, a1, 16);
    a2 += __shfl_xor_sync(0xffffffffu, a2, 8);  a2 += __shfl_xor_sync(0xffffffffu, a2, 16);
    a3 += __shfl_xor_sync(0xffffffffu, a3, 8);  a3 += __shfl_xor_sync(0xffffffffu, a3, 16);
    a4 += __shfl_xor_sync(0xffffffffu, a4, 8);  a4 += __shfl_xor_sync(0xffffffffu, a4, 16);
    a5 += __shfl_xor_sync(0xffffffffu, a5, 8);  a5 += __shfl_xor_sync(0xffffffffu, a5, 16);
    a6 += __shfl_xor_sync(0xffffffffu, a6, 8);  a6 += __shfl_xor_sync(0xffffffffu, a6, 16);
    a7 += __shfl_xor_sync(0xffffffffu, a7, 8);  a7 += __shfl_xor_sync(0xffffffffu, a7, 16);

    if (g == 0) {
        float4* op = (float4*)(out + (size_t)wid * DIM) + l8 * 2;
        op[0] = make_float4(fmaxf(a0, 0.f), fmaxf(a1, 0.f),
                            fmaxf(a2, 0.f), fmaxf(a3, 0.f));
        op[1] = make_float4(fmaxf(a4, 0.f), fmaxf(a5, 0.f),
                            fmaxf(a6, 0.f), fmaxf(a7, 0.f));
    }
}

// ---------------------------------------------------------------------------
// Launch: fork a side stream so the bucket build (memset + perm_u + perm_i,
// atomic-latency-bound, issue ~2%) runs CONCURRENTLY with the GEMM
// (FMA-bound). Standard event fork/join -- graph capture records this as
// two parallel branches. Streams/events are host-side objects (no device
// allocation); they are created fresh each call and intentionally not
// destroyed while a capture may be active.
// ---------------------------------------------------------------------------
extern "C" void kernel_launch(void* const* d_in, const int* in_sizes, int n_in,
                              void* d_out, int out_size)
{
    const float* user_x  = (const float*)d_in[0];
    const float* item_x  = (const float*)d_in[1];
    const float* user_w  = (const float*)d_in[2];
    const float* item_w  = (const float*)d_in[3];
    const int*   ui_rows = (const int*)d_in[4];
    const int*   ui_cols = (const int*)d_in[5];
    const float* ui_vals = (const float*)d_in[6];

    float* out = (float*)d_out;

    void* p_cnt = nullptr;
    cudaGetSymbolAddress(&p_cnt, g_cnt);

    cudaStream_t s2;
    cudaEvent_t  ev_fork, ev_join;
    cudaStreamCreateWithFlags(&s2, cudaStreamNonBlocking);
    cudaEventCreateWithFlags(&ev_fork, cudaEventDisableTiming);
    cudaEventCreateWithFlags(&ev_join, cudaEventDisableTiming);

    // fork s2 off the main (captured) stream
    cudaEventRecord(ev_fork, 0);
    cudaStreamWaitEvent(s2, ev_fork, 0);

    // --- branch A (main stream): both dense GEMMs (fp16 outputs) ---
    gemm_both_kernel<<<NB_U + NB_I, 256>>>(user_x, user_w, item_x, item_w);

    // --- branch B (side stream): zero cursors, bucket both directions ---
    cudaMemsetAsync(p_cnt, 0, N_ROWS * sizeof(int), s2);
    perm_user_kernel<<<(NNZ_C + 255) / 256, 256, 0, s2>>>(ui_rows, ui_cols, ui_vals);
    perm_item_kernel<<<(NNZ_C + 255) / 256, 256, 0, s2>>>(ui_rows, ui_cols, ui_vals);

    // join s2 back into the main stream
    cudaEventRecord(ev_join, s2);
    cudaStreamWaitEvent(0, ev_join, 0);

    // gather SpMM with fused ReLU (needs both branches)
    spmm_gather_kernel<<<(N_ROWS * 32 + 255) / 256, 256>>>(out);
}

// round 13
// speedup vs baseline: 1.2645x; 1.0645x over previous
#include <cuda_runtime.h>
#include <cuda_fp16.h>
#include <cstdint>

#define N_USERS 100000
#define N_ITEMS 50000
#define N_ROWS  150000          // users then items, matching d_out layout
#define NNZ_C   1600000
#define DIM     64

#define NBT_U   782             // ceil(100000/128) user tensor-gemm blocks
#define NBT_I   391             // ceil(50000/128)  item tensor-gemm blocks

#define CAP_U   96              // max user degree (Poisson(16): P(>=96) ~ 1e-40)
#define CAP_I   128             // max item degree (Poisson(32))

// ---- device scratch (no-alloc rule) ----
__device__ __half g_xw_user[(size_t)N_USERS * DIM];        // 12.8 MB
__device__ __half g_xw_item[(size_t)N_ITEMS * DIM];        //  6.4 MB
__device__ int    g_cnt[N_ROWS];                           // degree cursors
__device__ int2   g_perm_u[(size_t)N_USERS * CAP_U];       // 76.8 MB (src_item, val)
__device__ int2   g_perm_i[(size_t)N_ITEMS * CAP_I];       // 51.2 MB (src_user, val)

__device__ __forceinline__ uint32_t f2tf32(float f) {
    uint32_t r;
    asm("cvt.rna.tf32.f32 %0, %1;" : "=r"(r) : "f"(f));
    return r;
}

// ---------------------------------------------------------------------------
// Tensor-core GEMM (tf32 mma.sync m16n8k8): Y = X @ W, K = N = 64,
// fp32 accumulate, fp16 output. 128 rows per 256-thread block (16 per warp).
// Blocks [0, NBT_U) -> user matrix, rest -> item matrix.
// W lives in smem as pre-converted tf32 bits, [k][n] row-major: the B-frag
// LDS pattern (4 lanes share one address per n) is a conflict-free broadcast.
// ---------------------------------------------------------------------------
__global__ __launch_bounds__(256) void gemm_tc_kernel(
    const float* __restrict__ user_x, const float* __restrict__ user_w,
    const float* __restrict__ item_x, const float* __restrict__ item_w)
{
    __shared__ uint32_t Ws[64 * 64];   // tf32 bits, [k][n]

    const int  tid     = threadIdx.x;
    const int  b       = blockIdx.x;
    const bool is_item = (b >= NBT_U);
    const int  gb      = is_item ? (b - NBT_U) : b;
    const int  nrows   = is_item ? N_ITEMS : N_USERS;
    const float* X     = is_item ? item_x : user_x;
    const float* W     = is_item ? item_w : user_w;
    __half*      Y     = is_item ? g_xw_item : g_xw_user;

    // load W -> tf32 bits in smem (4096 floats, 4 float4 per thread)
    {
        const float4* W4 = (const float4*)W;
        #pragma unroll
        for (int i = 0; i < 4; i++) {
            float4 v = W4[tid + i * 256];
            uint4 t;
            t.x = f2tf32(v.x); t.y = f2tf32(v.y);
            t.z = f2tf32(v.z); t.w = f2tf32(v.w);
            ((uint4*)Ws)[tid + i * 256] = t;
        }
    }
    __syncthreads();

    const int warp = tid >> 5;
    const int lane = tid & 31;
    const int gid  = lane >> 2;        // group id 0..7
    const int tig  = lane & 3;         // thread-in-group 0..3

    const int r0 = gb * 128 + warp * 16 + gid;     // rows gid, gid+8 of warp tile
    const int r1 = r0 + 8;
    const bool v0 = r0 < nrows;
    const bool v1 = r1 < nrows;
    const float* x0 = X + (size_t)r0 * DIM;
    const float* x1 = X + (size_t)r1 * DIM;

    float acc[8][4] = {};              // 8 n-tiles of 8 cols each

    #pragma unroll
    for (int kk = 0; kk < 8; kk++) {   // k in steps of 8
        const int kc = kk * 8 + tig;
        const float fa0 = v0 ? __ldg(x0 + kc)     : 0.f;
        const float fa1 = v1 ? __ldg(x1 + kc)     : 0.f;
        const float fa2 = v0 ? __ldg(x0 + kc + 4) : 0.f;
        const float fa3 = v1 ? __ldg(x1 + kc + 4) : 0.f;
        const uint32_t a0 = f2tf32(fa0);
        const uint32_t a1 = f2tf32(fa1);
        const uint32_t a2 = f2tf32(fa2);
        const uint32_t a3 = f2tf32(fa3);

        #pragma unroll
        for (int j = 0; j < 8; j++) {
            const uint32_t b0 = Ws[(kk * 8 + tig)     * 64 + j * 8 + gid];
            const uint32_t b1 = Ws[(kk * 8 + tig + 4) * 64 + j * 8 + gid];
            asm volatile(
                "mma.sync.aligned.m16n8k8.row.col.f32.tf32.tf32.f32 "
                "{%0,%1,%2,%3}, {%4,%5,%6,%7}, {%8,%9}, {%0,%1,%2,%3};"
                : "+f"(acc[j][0]), "+f"(acc[j][1]),
                  "+f"(acc[j][2]), "+f"(acc[j][3])
                : "r"(a0), "r"(a1), "r"(a2), "r"(a3), "r"(b0), "r"(b1));
        }
    }

    // epilogue: c0,c1 -> row r0 cols (2*tig, +1); c2,c3 -> row r1
    #pragma unroll
    for (int j = 0; j < 8; j++) {
        const int col = j * 8 + 2 * tig;
        if (v0)
            *(__half2*)(Y + (size_t)r0 * DIM + col) =
                __floats2half2_rn(acc[j][0], acc[j][1]);
        if (v1)
            *(__half2*)(Y + (size_t)r1 * DIM + col) =
                __floats2half2_rn(acc[j][2], acc[j][3]);
    }
}

// ---------------------------------------------------------------------------
// Bucket edges, BOTH directions in one pass (edge arrays read once).
// 1 edge/thread: maximize independent atomic+store chains in flight.
// ---------------------------------------------------------------------------
__global__ __launch_bounds__(256) void perm_both_kernel(
    const int* __restrict__ rows, const int* __restrict__ cols,
    const float* __restrict__ vals)
{
    int e = blockIdx.x * blockDim.x + threadIdx.x;
    if (e >= NNZ_C) return;
    int r = rows[e];
    int c = cols[e];
    int v = __float_as_int(vals[e]);
    int s0 = atomicAdd(&g_cnt[r], 1);
    g_perm_u[(size_t)r * CAP_U + s0] = make_int2(c, v);
    int s1 = atomicAdd(&g_cnt[N_USERS + c], 1);
    g_perm_i[(size_t)c * CAP_I + s1] = make_int2(r, v);
}

// ---------------------------------------------------------------------------
// SpMM gather (R11-proven): one warp per output row. 8-lane groups each
// process one edge per iteration; all 8 lanes load the same perm entry
// (L1 broadcast). Each lane owns 8 columns via one LDG.128 of fp16.
// fp32 accumulation, cross-group shfl_xor reduction, fused ReLU.
// ---------------------------------------------------------------------------
__global__ __launch_bounds__(256) void spmm_gather_kernel(float* __restrict__ out)
{
    const int wid  = (blockIdx.x * blockDim.x + threadIdx.x) >> 5;
    const int lane = threadIdx.x & 31;
    if (wid >= N_ROWS) return;

    const int g  = lane >> 3;
    const int l8 = lane & 7;

    const int n = g_cnt[wid];
    const int2* __restrict__ bkt;
    const __half* __restrict__ src;
    if (wid < N_USERS) {
        bkt = g_perm_u + (size_t)wid * CAP_U;
        src = g_xw_item;
    } else {
        bkt = g_perm_i + (size_t)(wid - N_USERS) * CAP_I;
        src = g_xw_user;
    }

    float a0 = 0.f, a1 = 0.f, a2 = 0.f, a3 = 0.f;
    float a4 = 0.f, a5 = 0.f, a6 = 0.f, a7 = 0.f;

    for (int k = g; k < n; k += 4) {
        int2 p = __ldg(bkt + k);                       // broadcast within group
        const float v = __int_as_float(p.y);
        uint4 h = __ldg((const uint4*)(src + (size_t)p.x * DIM) + l8);
        float2 f0 = __half22float2(*(__half2*)&h.x);
        float2 f1 = __half22float2(*(__half2*)&h.y);
        float2 f2 = __half22float2(*(__half2*)&h.z);
        float2 f3 = __half22float2(*(__half2*)&h.w);
        a0 += v * f0.x; a1 += v * f0.y;
        a2 += v * f1.x; a3 += v * f1.y;
        a4 += v * f2.x; a5 += v * f2.y;
        a6 += v * f3.x; a7 += v * f3.y;
    }

    // sum across the 4 edge-groups (lanes l8, l8+8, l8+16, l8+24 share cols)
    a0 += __shfl_xor_sync(0xffffffffu, a0, 8);  a0 += __shfl_xor_sync(0xffffffffu, a0, 16);
    a1 += __shfl_xor_sync(0xffffffffu, a1, 8);  a1 += __shfl_xor_sync(0xffffffffu, a1, 16);
    a2 += __shfl_xor_sync(0xffffffffu, a2, 8);  a2 += __shfl_xor_sync(0xffffffffu, a2, 16);
    a3 += __shfl_xor_sync(0xffffffffu, a3, 8);  a3 += __shfl_xor_sync(0xffffffffu, a3, 16);
    a4 += __shfl_xor_sync(0xffffffffu, a4, 8);  a4 += __shfl_xor_sync(0xffffffffu, a4, 16);
    a5 += __shfl_xor_sync(0xffffffffu, a5, 8);  a5 += __shfl_xor_sync(0xffffffffu, a5, 16);
    a6 += __shfl_xor_sync(0xffffffffu, a6, 8);  a6 += __shfl_xor_sync(0xffffffffu, a6, 16);
    a7 += __shfl_xor_sync(0xffffffffu, a7, 8);  a7 += __shfl_xor_sync(0xffffffffu, a7, 16);

    if (g == 0) {
        float4* op = (float4*)(out + (size_t)wid * DIM) + l8 * 2;
        op[0] = make_float4(fmaxf(a0, 0.f), fmaxf(a1, 0.f),
                            fmaxf(a2, 0.f), fmaxf(a3, 0.f));
        op[1] = make_float4(fmaxf(a4, 0.f), fmaxf(a5, 0.f),
                            fmaxf(a6, 0.f), fmaxf(a7, 0.f));
    }
}

// ---------------------------------------------------------------------------
// Serial launch on stream 0 only (no stream/event objects -- R12's leak).
// ---------------------------------------------------------------------------
extern "C" void kernel_launch(void* const* d_in, const int* in_sizes, int n_in,
                              void* d_out, int out_size)
{
    const float* user_x  = (const float*)d_in[0];
    const float* item_x  = (const float*)d_in[1];
    const float* user_w  = (const float*)d_in[2];
    const float* item_w  = (const float*)d_in[3];
    const int*   ui_rows = (const int*)d_in[4];
    const int*   ui_cols = (const int*)d_in[5];
    const float* ui_vals = (const float*)d_in[6];

    float* out = (float*)d_out;

    void* p_cnt = nullptr;
    cudaGetSymbolAddress(&p_cnt, g_cnt);

    // zero degree cursors
    cudaMemsetAsync(p_cnt, 0, N_ROWS * sizeof(int), 0);

    // both dense GEMMs on tensor cores (tf32, fp16 outputs)
    gemm_tc_kernel<<<NBT_U + NBT_I, 256>>>(user_x, user_w, item_x, item_w);

    // bucket edges, both directions, one pass over the edge list
    perm_both_kernel<<<(NNZ_C + 255) / 256, 256>>>(ui_rows, ui_cols, ui_vals);

    // gather SpMM with fused ReLU (writes every output row)
    spmm_gather_kernel<<<(N_ROWS * 32 + 255) / 256, 256>>>(out);
}

// round 14
// speedup vs baseline: 1.3707x; 1.0840x over previous
#include <cuda_runtime.h>
#include <cuda_fp16.h>
#include <cstdint>

#define N_USERS 100000
#define N_ITEMS 50000
#define N_ROWS  150000          // users then items, matching d_out layout
#define NNZ_C   1600000
#define DIM     64

#define ROWS_PER_BLK 64
#define NBT_U   1563            // ceil(100000/64) user tensor-gemm blocks
#define NBT_I   782             // ceil(50000/64)  item tensor-gemm blocks

#define CAP_U   96              // max user degree (Poisson(16): P(>=96) ~ 1e-40)
#define CAP_I   128             // max item degree (Poisson(32))

// ---- device scratch (no-alloc rule) ----
__device__ __half g_xw_user[(size_t)N_USERS * DIM];        // 12.8 MB
__device__ __half g_xw_item[(size_t)N_ITEMS * DIM];        //  6.4 MB
__device__ int    g_cnt[N_ROWS];                           // degree cursors
__device__ int2   g_perm_u[(size_t)N_USERS * CAP_U];       // 76.8 MB (src_item, val)
__device__ int2   g_perm_i[(size_t)N_ITEMS * CAP_I];       // 51.2 MB (src_user, val)

__device__ __forceinline__ uint32_t f2tf32(float f) {
    uint32_t r;
    asm("cvt.rna.tf32.f32 %0, %1;" : "=r"(r) : "f"(f));
    return r;
}

// ---------------------------------------------------------------------------
// Tensor-core GEMM (tf32 mma.sync m16n8k8): Y = X @ W, K = N = 64,
// fp32 accumulate, fp16 output. 64 rows per 128-thread block (16 per warp).
//
// Data feeding (the R13 bottleneck) fixed:
//  - X tile staged in smem via coalesced float4 loads, stored as tf32 bits
//    with row stride 68 words -> A-frag scalar LDS hits all 32 banks
//    (bank = (4*gid + tig) mod 32, all distinct).
//  - W pre-packed into lane-major B-fragment layout Wp[kk][lane][16] padded
//    to 20 words/lane -> 4x LDS.128 per kk (vs 16x LDS.32), and lane*20
//    mod 32 cycles through {0,20,8,28,16,4,24,12} -> conflict-free phases.
// ---------------------------------------------------------------------------
__global__ __launch_bounds__(128) void gemm_tc_kernel(
    const float* __restrict__ user_x, const float* __restrict__ user_w,
    const float* __restrict__ item_x, const float* __restrict__ item_w)
{
    __shared__ uint32_t Xs[ROWS_PER_BLK * 68];     // tf32 bits, stride 68
    __shared__ uint32_t Wp[8 * 32 * 20];           // packed B frags, stride 20

    const int  tid     = threadIdx.x;
    const int  b       = blockIdx.x;
    const bool is_item = (b >= NBT_U);
    const int  gb      = is_item ? (b - NBT_U) : b;
    const int  nrows   = is_item ? N_ITEMS : N_USERS;
    const float* X     = is_item ? item_x : user_x;
    const float* W     = is_item ? item_w : user_w;
    __half*      Y     = is_item ? g_xw_item : g_xw_user;
    const int  row0    = gb * ROWS_PER_BLK;

    // ---- pack W into lane-major B-fragment layout (one-time, 16/iter) ----
    for (int idx = tid; idx < 8 * 32; idx += 128) {
        const int kk  = idx >> 5;
        const int ln  = idx & 31;
        const int gid = ln >> 2;
        const int tig = ln & 3;
        uint32_t* dst = Wp + kk * 640 + ln * 20;
        #pragma unroll
        for (int j = 0; j < 8; j++) {
            dst[j * 2 + 0] = f2tf32(W[(kk * 8 + tig)     * 64 + j * 8 + gid]);
            dst[j * 2 + 1] = f2tf32(W[(kk * 8 + tig + 4) * 64 + j * 8 + gid]);
        }
    }

    // ---- stage X tile (64 rows x 64 cols), coalesced, tf32 bits ----
    #pragma unroll
    for (int i = 0; i < 8; i++) {
        const int idx = tid + i * 128;             // float4 index in tile
        const int r   = idx >> 4;
        const int c4  = (idx & 15) * 4;
        float4 v = make_float4(0.f, 0.f, 0.f, 0.f);
        if (row0 + r < nrows)
            v = *(const float4*)(X + (size_t)(row0 + r) * DIM + c4);
        uint32_t* dst = Xs + r * 68 + c4;
        dst[0] = f2tf32(v.x); dst[1] = f2tf32(v.y);
        dst[2] = f2tf32(v.z); dst[3] = f2tf32(v.w);
    }
    __syncthreads();

    const int warp = tid >> 5;                     // 0..3 -> rows warp*16..+15
    const int lane = tid & 31;
    const int gid  = lane >> 2;
    const int tig  = lane & 3;
    const int wrow = warp * 16;

    float acc[8][4] = {};

    #pragma unroll
    for (int kk = 0; kk < 8; kk++) {
        const int kc = kk * 8 + tig;
        const uint32_t a0 = Xs[(wrow + gid)     * 68 + kc];
        const uint32_t a1 = Xs[(wrow + gid + 8) * 68 + kc];
        const uint32_t a2 = Xs[(wrow + gid)     * 68 + kc + 4];
        const uint32_t a3 = Xs[(wrow + gid + 8) * 68 + kc + 4];

        const uint4* wp4 = (const uint4*)(Wp + kk * 640 + lane * 20);
        const uint4 b01 = wp4[0];
        const uint4 b23 = wp4[1];
        const uint4 b45 = wp4[2];
        const uint4 b67 = wp4[3];

        #define MMA8(J, BH0, BH1)                                            \
            asm volatile(                                                    \
                "mma.sync.aligned.m16n8k8.row.col.f32.tf32.tf32.f32 "        \
                "{%0,%1,%2,%3}, {%4,%5,%6,%7}, {%8,%9}, {%0,%1,%2,%3};"      \
                : "+f"(acc[J][0]), "+f"(acc[J][1]),                          \
                  "+f"(acc[J][2]), "+f"(acc[J][3])                           \
                : "r"(a0), "r"(a1), "r"(a2), "r"(a3), "r"(BH0), "r"(BH1))
        MMA8(0, b01.x, b01.y);
        MMA8(1, b01.z, b01.w);
        MMA8(2, b23.x, b23.y);
        MMA8(3, b23.z, b23.w);
        MMA8(4, b45.x, b45.y);
        MMA8(5, b45.z, b45.w);
        MMA8(6, b67.x, b67.y);
        MMA8(7, b67.z, b67.w);
        #undef MMA8
    }

    // epilogue: c0,c1 -> row r0 cols (2*tig, +1); c2,c3 -> row r1
    const int r0 = row0 + wrow + gid;
    const int r1 = r0 + 8;
    const bool v0 = r0 < nrows;
    const bool v1 = r1 < nrows;
    #pragma unroll
    for (int j = 0; j < 8; j++) {
        const int col = j * 8 + 2 * tig;
        if (v0)
            *(__half2*)(Y + (size_t)r0 * DIM + col) =
                __floats2half2_rn(acc[j][0], acc[j][1]);
        if (v1)
            *(__half2*)(Y + (size_t)r1 * DIM + col) =
                __floats2half2_rn(acc[j][2], acc[j][3]);
    }
}

// ---------------------------------------------------------------------------
// Bucket edges, BOTH directions in one pass (edge arrays read once).
// 1 edge/thread: maximize independent atomic+store chains in flight.
// ---------------------------------------------------------------------------
__global__ __launch_bounds__(256) void perm_both_kernel(
    const int* __restrict__ rows, const int* __restrict__ cols,
    const float* __restrict__ vals)
{
    int e = blockIdx.x * blockDim.x + threadIdx.x;
    if (e >= NNZ_C) return;
    int r = rows[e];
    int c = cols[e];
    int v = __float_as_int(vals[e]);
    int s0 = atomicAdd(&g_cnt[r], 1);
    g_perm_u[(size_t)r * CAP_U + s0] = make_int2(c, v);
    int s1 = atomicAdd(&g_cnt[N_USERS + c], 1);
    g_perm_i[(size_t)c * CAP_I + s1] = make_int2(r, v);
}

// ---------------------------------------------------------------------------
// SpMM gather (proven): one warp per output row. 8-lane groups each process
// one edge per iteration; all 8 lanes load the same perm entry (L1
// broadcast). Each lane owns 8 columns via one LDG.128 of fp16. fp32
// accumulation, cross-group shfl_xor reduction, fused ReLU.
// ---------------------------------------------------------------------------
__global__ __launch_bounds__(256) void spmm_gather_kernel(float* __restrict__ out)
{
    const int wid  = (blockIdx.x * blockDim.x + threadIdx.x) >> 5;
    const int lane = threadIdx.x & 31;
    if (wid >= N_ROWS) return;

    const int g  = lane >> 3;
    const int l8 = lane & 7;

    const int n = g_cnt[wid];
    const int2* __restrict__ bkt;
    const __half* __restrict__ src;
    if (wid < N_USERS) {
        bkt = g_perm_u + (size_t)wid * CAP_U;
        src = g_xw_item;
    } else {
        bkt = g_perm_i + (size_t)(wid - N_USERS) * CAP_I;
        src = g_xw_user;
    }

    float a0 = 0.f, a1 = 0.f, a2 = 0.f, a3 = 0.f;
    float a4 = 0.f, a5 = 0.f, a6 = 0.f, a7 = 0.f;

    for (int k = g; k < n; k += 4) {
        int2 p = __ldg(bkt + k);                       // broadcast within group
        const float v = __int_as_float(p.y);
        uint4 h = __ldg((const uint4*)(src + (size_t)p.x * DIM) + l8);
        float2 f0 = __half22float2(*(__half2*)&h.x);
        float2 f1 = __half22float2(*(__half2*)&h.y);
        float2 f2 = __half22float2(*(__half2*)&h.z);
        float2 f3 = __half22float2(*(__half2*)&h.w);
        a0 += v * f0.x; a1 += v * f0.y;
        a2 += v * f1.x; a3 += v * f1.y;
        a4 += v * f2.x; a5 += v * f2.y;
        a6 += v * f3.x; a7 += v * f3.y;
    }

    // sum across the 4 edge-groups (lanes l8, l8+8, l8+16, l8+24 share cols)
    a0 += __shfl_xor_sync(0xffffffffu, a0, 8);  a0 += __shfl_xor_sync(0xffffffffu, a0, 16);
    a1 += __shfl_xor_sync(0xffffffffu, a1, 8);  a1 += __shfl_xor_sync(0xffffffffu, a1, 16);
    a2 += __shfl_xor_sync(0xffffffffu, a2, 8);  a2 += __shfl_xor_sync(0xffffffffu, a2, 16);
    a3 += __shfl_xor_sync(0xffffffffu, a3, 8);  a3 += __shfl_xor_sync(0xffffffffu, a3, 16);
    a4 += __shfl_xor_sync(0xffffffffu, a4, 8);  a4 += __shfl_xor_sync(0xffffffffu, a4, 16);
    a5 += __shfl_xor_sync(0xffffffffu, a5, 8);  a5 += __shfl_xor_sync(0xffffffffu, a5, 16);
    a6 += __shfl_xor_sync(0xffffffffu, a6, 8);  a6 += __shfl_xor_sync(0xffffffffu, a6, 16);
    a7 += __shfl_xor_sync(0xffffffffu, a7, 8);  a7 += __shfl_xor_sync(0xffffffffu, a7, 16);

    if (g == 0) {
        float4* op = (float4*)(out + (size_t)wid * DIM) + l8 * 2;
        op[0] = make_float4(fmaxf(a0, 0.f), fmaxf(a1, 0.f),
                            fmaxf(a2, 0.f), fmaxf(a3, 0.f));
        op[1] = make_float4(fmaxf(a4, 0.f), fmaxf(a5, 0.f),
                            fmaxf(a6, 0.f), fmaxf(a7, 0.f));
    }
}

// ---------------------------------------------------------------------------
// Serial launch on stream 0 only (no stream/event objects).
// ---------------------------------------------------------------------------
extern "C" void kernel_launch(void* const* d_in, const int* in_sizes, int n_in,
                              void* d_out, int out_size)
{
    const float* user_x  = (const float*)d_in[0];
    const float* item_x  = (const float*)d_in[1];
    const float* user_w  = (const float*)d_in[2];
    const float* item_w  = (const float*)d_in[3];
    const int*   ui_rows = (const int*)d_in[4];
    const int*   ui_cols = (const int*)d_in[5];
    const float* ui_vals = (const float*)d_in[6];

    float* out = (float*)d_out;

    void* p_cnt = nullptr;
    cudaGetSymbolAddress(&p_cnt, g_cnt);

    // zero degree cursors
    cudaMemsetAsync(p_cnt, 0, N_ROWS * sizeof(int), 0);

    // both dense GEMMs on tensor cores (tf32, fp16 outputs)
    gemm_tc_kernel<<<NBT_U + NBT_I, 128>>>(user_x, user_w, item_x, item_w);

    // bucket edges, both directions, one pass over the edge list
    perm_both_kernel<<<(NNZ_C + 255) / 256, 256>>>(ui_rows, ui_cols, ui_vals);

    // gather SpMM with fused ReLU (writes every output row)
    spmm_gather_kernel<<<(N_ROWS * 32 + 255) / 256, 256>>>(out);
}